// round 13
// baseline (speedup 1.0000x reference)
#include <cuda_runtime.h>
#include <math.h>

// FFM forward, slot-major fused gather + 2-batch-per-warp combine:
//  K1 phases (block ranges => rough temporal phases, L2-friendly working sets):
//    [0, 5*BPS)       field-3 slots 0..4 (6.4MB subtable/slot); slot0 also feat3
//    [5*BPS, 10*BPS)  field-2 slots 0..4 (32MB subtable/slot);  slot0 also feat2
//  K2: each warp owns TWO batch elements (doubled memory-level parallelism in
//      the latency-bound gather chain), 1-step fields consumed directly.

#define WPB   8
#define BATCH 16384
#define BPS   (BATCH / WPB)   // 2048 blocks per slot phase

__device__ __align__(16) float g_v2[BATCH * 80];   // 5 slots x 16
__device__ __align__(16) float g_v3[BATCH * 80];
__device__ float g_feat2[BATCH];
__device__ float g_feat3[BATCH];

__constant__ int c_pair_i[15] = {0,0,0,0,0,1,1,1,1,2,2,2,3,3,4};
__constant__ int c_pair_j[15] = {1,2,3,4,5,2,3,4,5,3,4,5,4,5,5};

// One warp = one (batch, slot). dg = lane>>2 (8 draw groups), chunk = lane&3.
template<int SEQN>
__device__ __forceinline__ void slot_gather(
    const int* __restrict__ x, const float* __restrict__ E,
    const float* __restrict__ L, float* __restrict__ vout,
    float* __restrict__ featout, int dim, float inv, int slot, int b, int lane)
{
    const int dg    = lane >> 2;
    const int chunk = lane & 3;

    int ia = 0, ib = 0;
    if (lane < (SEQN < 32 ? SEQN : 32)) ia = __ldg(x + (size_t)b * SEQN + lane);
    if (SEQN > 32 && lane < SEQN - 32)  ib = __ldg(x + (size_t)b * SEQN + 32 + lane);

    const float* base = E + (size_t)slot * dim * 16 + chunk * 4;
    float4 acc = make_float4(0.f, 0.f, 0.f, 0.f);

#pragma unroll
    for (int t = 0; t < (SEQN + 7) / 8; ++t) {
        const int d = t * 8 + dg;
        const int idx = (d < 32) ? __shfl_sync(0xffffffffu, ia, d)
                                 : __shfl_sync(0xffffffffu, ib, d - 32);
        if (d < SEQN) {
            const float4 e = __ldg((const float4*)(base + (size_t)idx * 16));
            acc.x += e.x; acc.y += e.y; acc.z += e.z; acc.w += e.w;
        }
    }
#pragma unroll
    for (int off = 4; off <= 16; off <<= 1) {
        acc.x += __shfl_xor_sync(0xffffffffu, acc.x, off);
        acc.y += __shfl_xor_sync(0xffffffffu, acc.y, off);
        acc.z += __shfl_xor_sync(0xffffffffu, acc.z, off);
        acc.w += __shfl_xor_sync(0xffffffffu, acc.w, off);
    }
    if (lane < 4) {
        float4 r = make_float4(acc.x * inv, acc.y * inv, acc.z * inv, acc.w * inv);
        ((float4*)(vout + (size_t)b * 80 + slot * 16))[lane] = r;
    }

    // slot-0 phase also produces this field's linear feat (indices already in
    // registers; L table is small and L2-resident).
    if (slot == 0) {
        float p = 0.f;
        if (lane < (SEQN < 32 ? SEQN : 32)) p  = __ldg(L + ia);
        if (SEQN > 32 && lane < SEQN - 32)  p += __ldg(L + ib);
#pragma unroll
        for (int off = 16; off; off >>= 1)
            p += __shfl_xor_sync(0xffffffffu, p, off);
        if (lane == 0) featout[b] = p * inv;
    }
}

extern "C" __global__ void __launch_bounds__(WPB * 32)
ffm_gather_fused(const int* __restrict__ x2, const float* __restrict__ E2,
                 const float* __restrict__ L2,
                 const int* __restrict__ x3, const float* __restrict__ E3,
                 const float* __restrict__ L3)
{
    const int warp = threadIdx.x >> 5;
    const int lane = threadIdx.x & 31;

    int bid = blockIdx.x;
    if (bid < 5 * BPS) {
        const int slot = bid / BPS;
        const int bx   = bid - slot * BPS;
        slot_gather<20>(x3, E3, L3, g_v3, g_feat3, 100000, 0.05f,
                        slot, bx * WPB + warp, lane);
    } else {
        bid -= 5 * BPS;
        const int slot = bid / BPS;
        const int bx   = bid - slot * BPS;
        slot_gather<50>(x2, E2, L2, g_v2, g_feat2, 500000, 0.02f,
                        slot, bx * WPB + warp, lane);
    }
}

// ---------------- K2: combine, TWO batch elements per warp ----------------
extern "C" __global__ void __launch_bounds__(WPB * 32)
ffm_combine(const int* __restrict__ x0, const int* __restrict__ x1,
            const int* __restrict__ x4, const int* __restrict__ x5,
            const float* __restrict__ E0, const float* __restrict__ E1,
            const float* __restrict__ E4, const float* __restrict__ E5,
            const float* __restrict__ L0, const float* __restrict__ L1,
            const float* __restrict__ L4, const float* __restrict__ L5,
            const float* __restrict__ Wd, const float* __restrict__ bd,
            float* __restrict__ out)
{
    __shared__ __align__(16) float sv[WPB][2][6 * 80];
    __shared__ float sfeat[WPB][2][8];

    const int warp = threadIdx.x >> 5;
    const int lane = threadIdx.x & 31;
    const int b0 = (blockIdx.x * WPB + warp) * 2;   // handles b0, b0+1

    const int slot  = lane >> 2;
    const int chunk = lane & 3;

    // ---- independent loads for BOTH batches issued up front ----
    const int idx0a = __ldg(x0 + b0),     idx0b = __ldg(x0 + b0 + 1);
    const int idx1a = __ldg(x1 + b0),     idx1b = __ldg(x1 + b0 + 1);
    const int idx4a = __ldg(x4 + b0),     idx4b = __ldg(x4 + b0 + 1);
    const int idx5a = __ldg(x5 + b0),     idx5b = __ldg(x5 + b0 + 1);

    if (lane < 20) {
#pragma unroll
        for (int bb = 0; bb < 2; ++bb) {
            const int i0 = bb ? idx0b : idx0a;
            const int i1 = bb ? idx1b : idx1a;
            const int i4 = bb ? idx4b : idx4a;
            const int i5 = bb ? idx5b : idx5a;
            const size_t b = b0 + bb;
            const float4 e0 = __ldg((const float4*)(E0 + ((size_t)slot * 1000000 + i0) * 16) + chunk);
            const float4 e1 = __ldg((const float4*)(E1 + ((size_t)slot * 500000  + i1) * 16) + chunk);
            const float4 e4 = __ldg((const float4*)(E4 + ((size_t)slot * 10000   + i4) * 16) + chunk);
            const float4 e5 = __ldg((const float4*)(E5 + ((size_t)slot * 1000    + i5) * 16) + chunk);
            const float4 w2 = ((const float4*)(g_v2 + b * 80))[lane];
            const float4 w3 = ((const float4*)(g_v3 + b * 80))[lane];
            float* v = sv[warp][bb];
            ((float4*)(v + 0 * 80))[lane] = e0;
            ((float4*)(v + 1 * 80))[lane] = e1;
            ((float4*)(v + 4 * 80))[lane] = e4;
            ((float4*)(v + 5 * 80))[lane] = e5;
            ((float4*)(v + 2 * 80))[lane] = w2;
            ((float4*)(v + 3 * 80))[lane] = w3;
        }
    } else if (lane == 20) sfeat[warp][0][0] = __ldg(L0 + idx0a);
    else if (lane == 21)   sfeat[warp][0][1] = __ldg(L1 + idx1a);
    else if (lane == 22)   sfeat[warp][0][4] = __ldg(L4 + idx4a);
    else if (lane == 23)   sfeat[warp][0][5] = __ldg(L5 + idx5a);
    else if (lane == 24)   sfeat[warp][1][0] = __ldg(L0 + idx0b);
    else if (lane == 25)   sfeat[warp][1][1] = __ldg(L1 + idx1b);
    else if (lane == 26)   sfeat[warp][1][4] = __ldg(L4 + idx4b);
    else if (lane == 27)   sfeat[warp][1][5] = __ldg(L5 + idx5b);
    else if (lane == 28) { sfeat[warp][0][2] = g_feat2[b0];
                           sfeat[warp][0][3] = g_feat3[b0]; }
    else if (lane == 29) { sfeat[warp][1][2] = g_feat2[b0 + 1];
                           sfeat[warp][1][3] = g_feat3[b0 + 1]; }
    __syncwarp();

    // ---- pair interactions per batch: 15 pairs x 4 chunks = 60 items ----
#pragma unroll
    for (int bb = 0; bb < 2; ++bb) {
        const float* v = sv[warp][bb];
        float partial = 0.f;
#pragma unroll
        for (int r = 0; r < 2; ++r) {
            const int item = lane + r * 32;
            if (item < 60) {
                const int t = item >> 2;
                const int c = item & 3;
                const int i = c_pair_i[t];
                const int j = c_pair_j[t];
                const float4 a  = *(const float4*)(v + i * 80 + (j - 1) * 16 + c * 4);
                const float4 bv = *(const float4*)(v + j * 80 +  i      * 16 + c * 4);
                partial += a.x * bv.x + a.y * bv.y + a.z * bv.z + a.w * bv.w;
            }
        }
#pragma unroll
        for (int off = 16; off; off >>= 1)
            partial += __shfl_xor_sync(0xffffffffu, partial, off);

        if (lane == 0) {
            const float* feat = sfeat[warp][bb];
            float lin = __ldg(bd);
#pragma unroll
            for (int i = 0; i < 6; ++i) lin += feat[i] * __ldg(Wd + i);
            lin = fmaxf(lin, 0.f);
            out[b0 + bb] = 1.0f / (1.0f + expf(-(lin + partial)));
        }
    }
}

extern "C" void kernel_launch(void* const* d_in, const int* in_sizes, int n_in,
                              void* d_out, int out_size)
{
    const int* xs[6];
    for (int i = 0; i < 6; ++i) xs[i] = (const int*)d_in[i];

    // Classify E/L by element count (robust to input ordering):
    // E_i has 80*DIM_i elements, L_i has DIM_i. Disjoint size sets.
    const float* E[6] = {0,0,0,0,0,0};
    const float* L[6] = {0,0,0,0,0,0};
    const float* Wd = 0;
    const float* bd = 0;
    int ei = 0, li = 0;
    for (int k = 6; k < n_in; ++k) {
        const long long sz = (long long)in_sizes[k];
        const float* p = (const float*)d_in[k];
        if (sz == 80000000LL || sz == 40000000LL || sz == 8000000LL ||
            sz == 800000LL   || sz == 80000LL) {
            if (ei < 6) E[ei++] = p;
        } else if (sz == 1000000LL || sz == 500000LL || sz == 100000LL ||
                   sz == 10000LL   || sz == 1000LL) {
            if (li < 6) L[li++] = p;
        } else if (sz == 6LL) {
            Wd = p;
        } else if (sz == 1LL) {
            bd = p;
        }
    }

    float* out = (float*)d_out;

    // K1: slot-major gathers (field 3 phases, then field 2 phases) + feat2/3
    ffm_gather_fused<<<BPS * 10, WPB * 32>>>(xs[2], E[2], L[2],
                                             xs[3], E[3], L[3]);
    // K2: combine, 2 batch elements per warp
    ffm_combine<<<BATCH / (WPB * 2), WPB * 32>>>(
        xs[0], xs[1], xs[4], xs[5],
        E[0], E[1], E[4], E[5],
        L[0], L[1], L[4], L[5],
        Wd, bd, out);
}

// round 15
// speedup vs baseline: 1.3647x; 1.3647x over previous
#include <cuda_runtime.h>
#include <math.h>

// FFM forward, slot-major fused gather + PDL-overlapped combine:
//  K1 phases (block ranges => rough temporal phases, L2-friendly working sets):
//    [0, 5*BPS)       field-3 slots 0..4 (6.4MB subtable/slot)
//    [5*BPS, 10*BPS)  field-2 slots 0..4 (32MB subtable/slot)
//  K2 (combine) launched with Programmatic Stream Serialization: its blocks
//  start during K1's drain, run all K1-independent gathers (1-step fields,
//  L-table feats), then cudaGridDependencySynchronize() before reading the
//  g_v2/g_v3 scratch. Falls back to plain stream order if PDL isn't honored.

#define WPB   8
#define BATCH 16384
#define BPS   (BATCH / WPB)   // 2048 blocks per slot phase

__device__ __align__(16) float g_v2[BATCH * 80];   // 5 slots x 16
__device__ __align__(16) float g_v3[BATCH * 80];

__constant__ int c_pair_i[15] = {0,0,0,0,0,1,1,1,1,2,2,2,3,3,4};
__constant__ int c_pair_j[15] = {1,2,3,4,5,2,3,4,5,3,4,5,4,5,5};

// One warp = one (batch, slot). dg = lane>>2 (8 draw groups), chunk = lane&3.
template<int SEQN>
__device__ __forceinline__ void slot_gather(
    const int* __restrict__ x, const float* __restrict__ E,
    float* __restrict__ vout, int dim, float inv, int slot, int b, int lane)
{
    const int dg    = lane >> 2;
    const int chunk = lane & 3;

    int ia = 0, ib = 0;
    if (lane < (SEQN < 32 ? SEQN : 32)) ia = __ldg(x + (size_t)b * SEQN + lane);
    if (SEQN > 32 && lane < SEQN - 32)  ib = __ldg(x + (size_t)b * SEQN + 32 + lane);

    const float* base = E + (size_t)slot * dim * 16 + chunk * 4;
    float4 acc = make_float4(0.f, 0.f, 0.f, 0.f);

#pragma unroll
    for (int t = 0; t < (SEQN + 7) / 8; ++t) {
        const int d = t * 8 + dg;
        const int idx = (d < 32) ? __shfl_sync(0xffffffffu, ia, d)
                                 : __shfl_sync(0xffffffffu, ib, d - 32);
        if (d < SEQN) {
            const float4 e = __ldg((const float4*)(base + (size_t)idx * 16));
            acc.x += e.x; acc.y += e.y; acc.z += e.z; acc.w += e.w;
        }
    }
#pragma unroll
    for (int off = 4; off <= 16; off <<= 1) {
        acc.x += __shfl_xor_sync(0xffffffffu, acc.x, off);
        acc.y += __shfl_xor_sync(0xffffffffu, acc.y, off);
        acc.z += __shfl_xor_sync(0xffffffffu, acc.z, off);
        acc.w += __shfl_xor_sync(0xffffffffu, acc.w, off);
    }
    if (lane < 4) {
        float4 r = make_float4(acc.x * inv, acc.y * inv, acc.z * inv, acc.w * inv);
        ((float4*)(vout + (size_t)b * 80 + slot * 16))[lane] = r;
    }
}

extern "C" __global__ void __launch_bounds__(WPB * 32)
ffm_gather_fused(const int* __restrict__ x2, const float* __restrict__ E2,
                 const int* __restrict__ x3, const float* __restrict__ E3,
                 float* __restrict__ v2, float* __restrict__ v3)
{
    const int warp = threadIdx.x >> 5;
    const int lane = threadIdx.x & 31;

    int bid = blockIdx.x;
    if (bid < 5 * BPS) {
        const int slot = bid / BPS;
        const int bx   = bid - slot * BPS;
        slot_gather<20>(x3, E3, v3, 100000, 0.05f, slot, bx * WPB + warp, lane);
    } else {
        bid -= 5 * BPS;
        const int slot = bid / BPS;
        const int bx   = bid - slot * BPS;
        slot_gather<50>(x2, E2, v2, 500000, 0.02f, slot, bx * WPB + warp, lane);
    }

#if __CUDA_ARCH__ >= 900
    cudaTriggerProgrammaticLaunchCompletion();
#endif
}

// ---------------- K2: combine (PDL-overlapped) ----------------
extern "C" __global__ void __launch_bounds__(WPB * 32)
ffm_combine(const int* __restrict__ x0, const int* __restrict__ x1,
            const int* __restrict__ x2, const int* __restrict__ x3,
            const int* __restrict__ x4, const int* __restrict__ x5,
            const float* __restrict__ E0, const float* __restrict__ E1,
            const float* __restrict__ E4, const float* __restrict__ E5,
            const float* __restrict__ L0, const float* __restrict__ L1,
            const float* __restrict__ L2, const float* __restrict__ L3,
            const float* __restrict__ L4, const float* __restrict__ L5,
            const float* __restrict__ Wd, const float* __restrict__ bd,
            float* __restrict__ out)
{
    __shared__ __align__(16) float sv[WPB][6 * 80];
    __shared__ float sfeat[WPB][8];

    const int warp = threadIdx.x >> 5;
    const int lane = threadIdx.x & 31;
    const int b = blockIdx.x * WPB + warp;
    if (b >= BATCH) return;

    float* v    = sv[warp];
    float* feat = sfeat[warp];

    const int slot  = lane >> 2;
    const int chunk = lane & 3;

    // ======== Phase A: everything independent of K1 (overlaps K1 via PDL) ====
    const int idx0 = __ldg(x0 + b);
    const int idx1 = __ldg(x1 + b);
    const int idx4 = __ldg(x4 + b);
    const int idx5 = __ldg(x5 + b);
    const int i2a  = __ldg(x2 + (size_t)b * 50 + lane);
    const int i2b  = (lane < 18) ? __ldg(x2 + (size_t)b * 50 + 32 + lane) : 0;
    const int i3   = (lane < 20) ? __ldg(x3 + (size_t)b * 20 + lane) : 0;

    float p2 = __ldg(L2 + i2a) + ((lane < 18) ? __ldg(L2 + i2b) : 0.f);
    float p3 = (lane < 20) ? __ldg(L3 + i3) : 0.f;

    if (lane < 20) {
        const float4 e0 = __ldg((const float4*)(E0 + ((size_t)slot * 1000000 + idx0) * 16) + chunk);
        const float4 e1 = __ldg((const float4*)(E1 + ((size_t)slot * 500000  + idx1) * 16) + chunk);
        const float4 e4 = __ldg((const float4*)(E4 + ((size_t)slot * 10000   + idx4) * 16) + chunk);
        const float4 e5 = __ldg((const float4*)(E5 + ((size_t)slot * 1000    + idx5) * 16) + chunk);
        ((float4*)(v + 0 * 80))[lane] = e0;
        ((float4*)(v + 1 * 80))[lane] = e1;
        ((float4*)(v + 4 * 80))[lane] = e4;
        ((float4*)(v + 5 * 80))[lane] = e5;
    } else if (lane == 20) feat[0] = __ldg(L0 + idx0);
    else if (lane == 21)   feat[1] = __ldg(L1 + idx1);
    else if (lane == 22)   feat[4] = __ldg(L4 + idx4);
    else if (lane == 23)   feat[5] = __ldg(L5 + idx5);

#pragma unroll
    for (int off = 16; off; off >>= 1) {
        p2 += __shfl_xor_sync(0xffffffffu, p2, off);
        p3 += __shfl_xor_sync(0xffffffffu, p3, off);
    }
    if (lane == 0) { feat[2] = p2 * 0.02f; feat[3] = p3 * 0.05f; }

    // ======== Phase B: wait for K1's writes, then consume scratch ========
#if __CUDA_ARCH__ >= 900
    cudaGridDependencySynchronize();
#endif

    if (lane < 20) {
        ((float4*)(v + 2 * 80))[lane] = ((const float4*)(g_v2 + (size_t)b * 80))[lane];
        ((float4*)(v + 3 * 80))[lane] = ((const float4*)(g_v3 + (size_t)b * 80))[lane];
    }
    __syncwarp();

    // pair interactions: 15 pairs x 4 chunks = 60 items
    float partial = 0.f;
#pragma unroll
    for (int r = 0; r < 2; ++r) {
        const int item = lane + r * 32;
        if (item < 60) {
            const int t = item >> 2;
            const int c = item & 3;
            const int i = c_pair_i[t];
            const int j = c_pair_j[t];
            const float4 a  = *(const float4*)(v + i * 80 + (j - 1) * 16 + c * 4);
            const float4 bb = *(const float4*)(v + j * 80 +  i      * 16 + c * 4);
            partial += a.x * bb.x + a.y * bb.y + a.z * bb.z + a.w * bb.w;
        }
    }
#pragma unroll
    for (int off = 16; off; off >>= 1)
        partial += __shfl_xor_sync(0xffffffffu, partial, off);

    if (lane == 0) {
        float lin = __ldg(bd);
#pragma unroll
        for (int i = 0; i < 6; ++i) lin += feat[i] * __ldg(Wd + i);
        lin = fmaxf(lin, 0.f);
        out[b] = 1.0f / (1.0f + expf(-(lin + partial)));
    }
}

extern "C" void kernel_launch(void* const* d_in, const int* in_sizes, int n_in,
                              void* d_out, int out_size)
{
    const int* xs[6];
    for (int i = 0; i < 6; ++i) xs[i] = (const int*)d_in[i];

    // Classify E/L by element count (robust to input ordering):
    // E_i has 80*DIM_i elements, L_i has DIM_i. Disjoint size sets.
    const float* E[6] = {0,0,0,0,0,0};
    const float* L[6] = {0,0,0,0,0,0};
    const float* Wd = 0;
    const float* bd = 0;
    int ei = 0, li = 0;
    for (int k = 6; k < n_in; ++k) {
        const long long sz = (long long)in_sizes[k];
        const float* p = (const float*)d_in[k];
        if (sz == 80000000LL || sz == 40000000LL || sz == 8000000LL ||
            sz == 800000LL   || sz == 80000LL) {
            if (ei < 6) E[ei++] = p;
        } else if (sz == 1000000LL || sz == 500000LL || sz == 100000LL ||
                   sz == 10000LL   || sz == 1000LL) {
            if (li < 6) L[li++] = p;
        } else if (sz == 6LL) {
            Wd = p;
        } else if (sz == 1LL) {
            bd = p;
        }
    }

    float* out = (float*)d_out;

    float* v2p; cudaGetSymbolAddress((void**)&v2p, g_v2);
    float* v3p; cudaGetSymbolAddress((void**)&v3p, g_v3);

    // K1: fused slot-major gathers (field 3 phases, then field 2 phases)
    ffm_gather_fused<<<BPS * 10, WPB * 32>>>(xs[2], E[2], xs[3], E[3], v2p, v3p);

    // K2: combine, launched with Programmatic Stream Serialization so its
    // K1-independent gathers overlap K1's drain. Correct under fallback too.
    {
        cudaLaunchConfig_t cfg = {};
        cfg.gridDim  = dim3(BPS, 1, 1);
        cfg.blockDim = dim3(WPB * 32, 1, 1);
        cfg.dynamicSmemBytes = 0;
        cfg.stream = 0;
        cudaLaunchAttribute attrs[1];
        attrs[0].id = cudaLaunchAttributeProgrammaticStreamSerialization;
        attrs[0].val.programmaticStreamSerializationAllowed = 1;
        cfg.attrs = attrs;
        cfg.numAttrs = 1;
        cudaError_t err = cudaLaunchKernelEx(&cfg, ffm_combine,
            xs[0], xs[1], xs[2], xs[3], xs[4], xs[5],
            E[0], E[1], E[4], E[5],
            L[0], L[1], L[2], L[3], L[4], L[5],
            Wd, bd, out);
        if (err != cudaSuccess) {
            // Fallback: plain launch (stream order still correct).
            ffm_combine<<<BPS, WPB * 32>>>(
                xs[0], xs[1], xs[2], xs[3], xs[4], xs[5],
                E[0], E[1], E[4], E[5],
                L[0], L[1], L[2], L[3], L[4], L[5],
                Wd, bd, out);
        }
    }
}